// round 17
// baseline (speedup 1.0000x reference)
#include <cuda_runtime.h>
#include <stdint.h>

// Shapes (fixed by the problem)
#define BATCH 32
#define SEQ   4096
#define VOCAB 10
#define FEAT  1024
#define DIM   64

#define CHUNK   256
#define THREADS 256
#define NPRODC  80                          // producer CTAs (8 pairs each)
#define NCONS   (BATCH * (SEQ / CHUNK))     // 512 consumer CTAs
#define NCTAS   (NPRODC + NCONS)            // 592 (all wave-1 resident)
#define NPAIRS  (DIM * VOCAB)               // 640

// Projected table P + per-producer-CTA flags (zeroed by graph memset node).
// Flags are 32B apart (separate sectors) to avoid slice hotspotting.
__device__ float    g_P[NPAIRS];
__device__ unsigned g_flag[NPRODC * 8];     // use stride 8 (32B per flag)

__device__ __forceinline__ unsigned ld_acq(const unsigned* p) {
    unsigned v;
    asm volatile("ld.acquire.gpu.global.u32 %0, [%1];" : "=r"(v) : "l"(p));
    return v;
}
__device__ __forceinline__ void st_rel(unsigned* p, unsigned v) {
    asm volatile("st.release.gpu.global.u32 [%0], %1;" :: "l"(p), "r"(v) : "memory");
}

// ---------------------------------------------------------------------------
// Single fused kernel.
//   CTAs [0,80):    producer — 8 warps, one (d,v) dot each (640 total),
//                   then ONE release-store to this CTA's own flag. No atomics.
//   CTAs [80,592):  consumer — prefetch indices, warp0 polls the 80 flags
//                   (spread over 80 cachelines -> no L2 hotspot), then the
//                   proven smem-staged gather.
// ---------------------------------------------------------------------------
__global__ void __launch_bounds__(THREADS)
fused_kernel(const int* __restrict__ idx,
             const float* __restrict__ fp,
             const float* __restrict__ W,
             const float* __restrict__ bias,
             float* __restrict__ out) {
    const int tid  = threadIdx.x;
    const int bid  = blockIdx.x;
    const int wid  = tid >> 5;
    const int lane = tid & 31;

    if (bid < NPRODC) {
        // ----- producer: one (d,v) pair per warp -----
        const int pid = bid * 8 + wid;       // 0..639
        const int d = pid / VOCAB;
        const int v = pid - d * VOCAB;

        const float4* fr = reinterpret_cast<const float4*>(fp + v * FEAT);
        const float4* wr = reinterpret_cast<const float4*>(W  + d * FEAT);

        float s = 0.f;
#pragma unroll
        for (int f = lane; f < FEAT / 4; f += 32) {   // 16 independent LDG.128
            float4 a = fr[f];
            float4 c = wr[f];
            s += a.x * c.x + a.y * c.y + a.z * c.z + a.w * c.w;
        }
#pragma unroll
        for (int o = 16; o > 0; o >>= 1)
            s += __shfl_down_sync(0xffffffffu, s, o);

        if (lane == 0)
            g_P[pid] = s + bias[d];

        __syncthreads();                      // all 8 pairs of this CTA stored
        if (tid == 0)
            st_rel(&g_flag[bid * 8], 1u);     // own cacheline, release order
        return;
    }

    // ----- consumer -----
    __shared__ float sP[NPAIRS];

    const int cid = bid - NPRODC;             // 0..511
    const int b   = cid >> 4;                 // 16 chunks per batch row
    const int l0  = (cid & 15) * CHUNK;
    const int lq  = tid & 63;                 // float4 slot (fixed per thread)
    const int db  = tid >> 6;                 // base d-row (0..3)

    // P-independent prefetch: this thread's 4 vocab indices (coalesced 16B)
    int4 iv = *reinterpret_cast<const int4*>(idx + b * SEQ + l0 + lq * 4);

    // Warp 0 polls all 80 flags; lanes cover <=3 flags each (distinct lines)
    if (wid == 0) {
        for (;;) {
            unsigned f0 = (lane      < NPRODC) ? ld_acq(&g_flag[lane * 8])        : 1u;
            unsigned f1 = (lane + 32 < NPRODC) ? ld_acq(&g_flag[(lane + 32) * 8]) : 1u;
            unsigned f2 = (lane + 64 < NPRODC) ? ld_acq(&g_flag[(lane + 64) * 8]) : 1u;
            if (__all_sync(0xffffffffu, f0 & f1 & f2)) break;
            __nanosleep(128);
        }
    }
    __syncthreads();

    // Table into shared: [d][v]
    for (int i = tid; i < NPAIRS; i += THREADS)
        sP[i] = g_P[i];
    __syncthreads();

    // Proven gather: 64 conflict-free LDS + 16 coalesced STG.128 per thread
    float* ob = out + (b * DIM) * SEQ + l0 + lq * 4;
#pragma unroll
    for (int k = 0; k < 16; k++) {
        const int d = db + 4 * k;
        const float* p = &sP[d * VOCAB];
        float4 r;
        r.x = p[iv.x];
        r.y = p[iv.y];
        r.z = p[iv.z];
        r.w = p[iv.w];
        *reinterpret_cast<float4*>(ob + d * SEQ) = r;
    }
}

// ---------------------------------------------------------------------------
// Graph per launch: [memset g_flag = 0] -> [fused_kernel]. Capture-legal,
// deterministic across replays (memset-node pattern validated in R13/R14).
// Inputs per metadata order: indices (int32), fp_table (f32), W (f32), b (f32)
// ---------------------------------------------------------------------------
extern "C" void kernel_launch(void* const* d_in, const int* in_sizes, int n_in,
                              void* d_out, int out_size) {
    const int*   idx  = (const int*)d_in[0];
    const float* fp   = (const float*)d_in[1];
    const float* W    = (const float*)d_in[2];
    const float* bias = (const float*)d_in[3];
    float*       out  = (float*)d_out;

    void* flag_addr = nullptr;
    cudaGetSymbolAddress(&flag_addr, g_flag);
    cudaMemsetAsync(flag_addr, 0, sizeof(unsigned) * NPRODC * 8, 0);

    fused_kernel<<<NCTAS, THREADS>>>(idx, fp, W, bias, out);
}